// round 10
// baseline (speedup 1.0000x reference)
#include <cuda_runtime.h>
#include <cuda_bf16.h>
#include <math.h>

#define KBINS 5
#define NBINS 7     // tail bin 0, 5 real bins, tail bin 6
#define NCELLS 13   // half-cells of width 0.5 over [-3.0, 3.5)
#define TAILB 2.5f
#define TPB 256
#define VPT 2       // float4 per thread

__device__ __forceinline__ float rcp_approx(float x) {
    float r; asm("rcp.approx.f32 %0, %1;" : "=f"(r) : "f"(x)); return r;
}
__device__ __forceinline__ float lg2_approx(float x) {
    float r; asm("lg2.approx.f32 %0, %1;" : "=f"(r) : "f"(x)); return r;
}

// Per-bin table (3 float4 stride = 48B -> bins hit distinct banks):
//   sh[3b+0] = A = {p2, p1, p0, q2}   den(x)  = p2 x^2 + p1 x + p0
//   sh[3b+1] = B = {q1, q0, r1, r0}   numz(x) = q2 x^2 + q1 x + q0 (y_k folded)
//                                     num2(x) = -p2 x^2 + r1 x + r0 (identity)
// Interior bins scaled by 1/s^2 so lj = log(num2/den^2) exactly.
// Tail bins (0,6): den=1, numz=x, num2=1 -> z=x, lj=0 exactly.
//
// Cell guess table sgd[c] = {bnd, bitcast(base_byte_off)}:
//   bin_byte_off(x in cell c) = base_off + (x > bnd) * 48.
// Valid because each half-cell contains at most one spline boundary.

__device__ __forceinline__ void rqs_one(
    float x, const float2* __restrict__ sgd,
    const char* __restrict__ shb, float& zo, float& lo)
{
    float t = fmaf(x, 2.0f, 6.0f);              // (x + 3) * 2
    int c = __float2int_rd(t);
    c = min(max(c, 0), NCELLS - 1);
    float2 g = sgd[c];
    int off = __float_as_int(g.y) + ((x > g.x) ? 48 : 0);

    float4 A = *(const float4*)(shb + off);
    float4 B = *(const float4*)(shb + off + 16);

    float den  = fmaf(fmaf(A.x, x, A.y), x, A.z);
    float numz = fmaf(fmaf(A.w, x, B.x), x, B.y);
    float num2 = fmaf(fmaf(-A.x, x, B.z), x, B.w);

    float rA = rcp_approx(den);
    zo = numz * rA;                              // y_k folded in; tail: x

    // lj = ln2*lg2(num2) - 2*ln2*lg2(den); tails: lg2(1)=0 exactly
    float l2d = lg2_approx(den);
    float l2n = lg2_approx(num2);
    lo = fmaf(l2n, 0.69314718056f, -1.3862943611f * l2d);
}

__global__ void __launch_bounds__(TPB)
rqs_fused_kernel(const float* __restrict__ x, const float* __restrict__ params,
                 float* __restrict__ out, int n4)
{
    __shared__ float4 sh[3 * NBINS];
    __shared__ float2 sgd[NCELLS];
    __shared__ float  sew[KBINS], seh[KBINS], sD[KBINS + 1];
    __shared__ float  scw[KBINS + 1], sch[KBINS + 1];

    int tid = threadIdx.x;
    int base = blockIdx.x * (TPB * VPT) + tid;
    bool full = (blockIdx.x + 1) * (TPB * VPT) <= n4;   // uniform per block

    const float4* __restrict__ x4 = (const float4*)x;
    float4* __restrict__ z4 = (float4*)out;
    float4* __restrict__ l4 = (float4*)(out + ((size_t)n4 * 4));

    // Issue x loads FIRST so their DRAM latency overlaps the table build.
    float4 xa, xb;
    if (full) {
        xa = x4[base];
        xb = x4[base + TPB];
    } else {
        if (base < n4)       xa = x4[base];
        if (base + TPB < n4) xb = x4[base + TPB];
    }

    // ---- fused table build, warp 0, parallel over lanes, fast-math ----
    if (tid < 32) {
        if (tid < KBINS) {
            sew[tid] = __expf(params[tid]);
            seh[tid] = __expf(params[KBINS + tid]);
        }
        if (tid < KBINS + 1) {
            float v = params[2 * KBINS + tid];
            sD[tid] = __logf(1.0f + __expf(-fabsf(v))) + fmaxf(v, 0.0f) + 1e-5f;
        }
        __syncwarp();
        if (tid == 0) {
            float sw = 0.f, shh = 0.f;
            #pragma unroll
            for (int i = 0; i < KBINS; i++) { sw += sew[i]; shh += seh[i]; }
            float iw = __fdividef(2.0f * TAILB, sw);
            float ih = __fdividef(2.0f * TAILB, shh);
            float aw = -TAILB, ah = -TAILB;
            scw[0] = -TAILB; sch[0] = -TAILB;
            #pragma unroll
            for (int i = 0; i < KBINS; i++) {
                aw = fmaf(sew[i], iw, aw); scw[i + 1] = aw;
                ah = fmaf(seh[i], ih, ah); sch[i + 1] = ah;
            }
        }
        __syncwarp();
        if (tid < KBINS) {
            int bi = tid;
            float xk = scw[bi], yk = sch[bi];
            float Wb = scw[bi + 1] - xk;
            float dy = sch[bi + 1] - yk;
            float dk = sD[bi], dk1 = sD[bi + 1];
            float s  = __fdividef(dy, Wb);
            float c  = dk + dk1 - 2.0f * s;
            float sd = s - dk;
            float a  = __fdividef(1.0f, Wb + 1e-8f);
            float b_ = -a * xk;

            float p2 = -c * a * a;
            float p1 = c * a * (1.0f - 2.0f * b_);
            float p0 = s + c * (b_ - b_ * b_);
            float q2 = dy * sd * a * a + yk * p2;
            float q1 = dy * a * (2.0f * b_ * sd + dk) + yk * p1;
            float q0 = dy * (sd * b_ * b_ + dk * b_) + yk * p0;
            float r1 = 2.0f * a * (c * b_ + sd);
            float r0 = c * b_ * b_ + 2.0f * sd * b_ + dk;

            float is2 = __fdividef(1.0f, s * s);
            sh[3 * (bi + 1) + 0] = make_float4(p2 * is2, p1 * is2, p0 * is2, q2 * is2);
            sh[3 * (bi + 1) + 1] = make_float4(q1 * is2, q0 * is2, r1 * is2, r0 * is2);
        } else if (tid < KBINS + 2) {
            // tail bins 0 and 6: den=1, numz=x, num2=1
            int bb = (tid == KBINS) ? 0 : (NBINS - 1);
            sh[3 * bb + 0] = make_float4(0.f, 0.f, 1.f, 0.f);
            sh[3 * bb + 1] = make_float4(1.f, 0.f, 0.f, 1.f);
        }
        __syncwarp();
        if (tid < NCELLS) {
            // Build half-cell guess table. Boundaries (transition at x > B):
            //   mB = nextafter(-2.5, -inf)  (encodes x >= -2.5)
            //   scw[1..4]                    (interior)
            //   +2.5                         (upper tail)
            float xL = 0.5f * (float)tid - 3.0f;
            float xR = xL + 0.5f;

            float mB = __int_as_float(__float_as_int(-TAILB) + 1);  // -2.5 - ulp

            // binOf(xL): bin index under the same compare semantics
            int b0 = (xL > mB);
            #pragma unroll
            for (int k = 1; k <= 4; k++) b0 += (xL > scw[k]);
            b0 += (xL > TAILB);

            float bnd = __int_as_float(0x7f800000);  // +inf: no boundary in cell
            if (mB >= xL && mB < xR) bnd = mB;
            #pragma unroll
            for (int k = 1; k <= 4; k++)
                if (scw[k] >= xL && scw[k] < xR) bnd = scw[k];
            if (TAILB >= xL && TAILB < xR) bnd = TAILB;

            sgd[tid] = make_float2(bnd, __int_as_float(b0 * 48));
        }
    }
    __syncthreads();
    // -------------------------------------------------------------------

    const char* shb = (const char*)sh;

    if (full) {
        float4 zv, lv;
        rqs_one(xa.x, sgd, shb, zv.x, lv.x);
        rqs_one(xa.y, sgd, shb, zv.y, lv.y);
        rqs_one(xa.z, sgd, shb, zv.z, lv.z);
        rqs_one(xa.w, sgd, shb, zv.w, lv.w);
        z4[base] = zv;
        l4[base] = lv;

        rqs_one(xb.x, sgd, shb, zv.x, lv.x);
        rqs_one(xb.y, sgd, shb, zv.y, lv.y);
        rqs_one(xb.z, sgd, shb, zv.z, lv.z);
        rqs_one(xb.w, sgd, shb, zv.w, lv.w);
        z4[base + TPB] = zv;
        l4[base + TPB] = lv;
    } else {
        if (base < n4) {
            float4 zv, lv;
            rqs_one(xa.x, sgd, shb, zv.x, lv.x);
            rqs_one(xa.y, sgd, shb, zv.y, lv.y);
            rqs_one(xa.z, sgd, shb, zv.z, lv.z);
            rqs_one(xa.w, sgd, shb, zv.w, lv.w);
            z4[base] = zv;
            l4[base] = lv;
        }
        if (base + TPB < n4) {
            float4 zv, lv;
            rqs_one(xb.x, sgd, shb, zv.x, lv.x);
            rqs_one(xb.y, sgd, shb, zv.y, lv.y);
            rqs_one(xb.z, sgd, shb, zv.z, lv.z);
            rqs_one(xb.w, sgd, shb, zv.w, lv.w);
            z4[base + TPB] = zv;
            l4[base + TPB] = lv;
        }
    }
}

extern "C" void kernel_launch(void* const* d_in, const int* in_sizes, int n_in,
                              void* d_out, int out_size)
{
    const float* x      = (const float*)d_in[0];
    const float* params = (const float*)d_in[1];
    float* out          = (float*)d_out;

    int n  = in_sizes[0];     // 16777216
    int n4 = n >> 2;          // float4 count

    int blocks = (n4 + TPB * VPT - 1) / (TPB * VPT);
    rqs_fused_kernel<<<blocks, TPB>>>(x, params, out, n4);
}

// round 11
// speedup vs baseline: 1.0183x; 1.0183x over previous
#include <cuda_runtime.h>
#include <cuda_bf16.h>
#include <math.h>

#define KBINS 5
#define NBINS 7     // tail bin 0, 5 real bins, tail bin 6
#define NCELLS 13   // half-cells of width 0.5 over [-3.0, 3.5)
#define TAILB 2.5f
#define TPB 256
#define VPT 2       // float4 per thread

__device__ __forceinline__ float rcp_approx(float x) {
    float r; asm("rcp.approx.f32 %0, %1;" : "=f"(r) : "f"(x)); return r;
}
__device__ __forceinline__ float lg2_approx(float x) {
    float r; asm("lg2.approx.f32 %0, %1;" : "=f"(r) : "f"(x)); return r;
}

// Per-bin table (3 float4 stride = 48B -> bins hit distinct banks), 6 coeffs:
//   sh[3b+0] = A = {p2, p1, p0, q2}   den(x)  = p2 x^2 + p1 x + p0
//   sh[3b+1].xy   = {q1, q0}          numz(x) = q2 x^2 + q1 x + q0 (y_k folded)
// z  = numz/den
// J  = dz/dx = (numz'*den - numz*den')/den^2   (y_k fold cancels in Wronskian)
// lj = ln2 * lg2(J)
// Tail bins (0,6): den=1, numz=x -> z=x, W=1, lj=0 exactly.
//
// Cell guess table sgd[c] = {bnd, bitcast(base_byte_off)}:
//   bin_byte_off(x in cell c) = base_off + (x > bnd) * 48.
// Valid because each half-cell contains at most one spline boundary.

__device__ __forceinline__ void rqs_one(
    float x, const float2* __restrict__ sgd,
    const char* __restrict__ shb, float& zo, float& lo)
{
    float t = fmaf(x, 2.0f, 6.0f);              // (x + 3) * 2
    int c = __float2int_rd(t);
    c = min(max(c, 0), NCELLS - 1);
    float2 g = sgd[c];
    int off = __float_as_int(g.y) + ((x > g.x) ? 48 : 0);

    float4 A = *(const float4*)(shb + off);
    float2 B = *(const float2*)(shb + off + 16);

    float x2   = x + x;
    float den  = fmaf(fmaf(A.x, x, A.y), x, A.z);
    float numz = fmaf(fmaf(A.w, x, B.x), x, B.y);
    float dd   = fmaf(A.x, x2, A.y);            // den'
    float nd   = fmaf(A.w, x2, B.x);            // numz'
    float t1   = numz * dd;
    float W    = fmaf(nd, den, -t1);            // J * den^2

    float rA = rcp_approx(den);
    zo = numz * rA;

    float la = (W * rA) * rA;                   // J; tails: 1
    lo = 0.69314718056f * lg2_approx(la);       // tails: 0
}

__global__ void __launch_bounds__(TPB)
rqs_fused_kernel(const float* __restrict__ x, const float* __restrict__ params,
                 float* __restrict__ out, int n4)
{
    __shared__ float4 sh[3 * NBINS];
    __shared__ float2 sgd[NCELLS];
    __shared__ float  sew[KBINS], seh[KBINS], sD[KBINS + 1];
    __shared__ float  scw[KBINS + 1], sch[KBINS + 1];

    int tid = threadIdx.x;
    int base = blockIdx.x * (TPB * VPT) + tid;
    bool full = (blockIdx.x + 1) * (TPB * VPT) <= n4;   // uniform per block

    const float4* __restrict__ x4 = (const float4*)x;
    float4* __restrict__ z4 = (float4*)out;
    float4* __restrict__ l4 = (float4*)(out + ((size_t)n4 * 4));

    // Issue x loads FIRST so their DRAM latency overlaps the table build.
    float4 xa, xb;
    if (full) {
        xa = x4[base];
        xb = x4[base + TPB];
    } else {
        if (base < n4)       xa = x4[base];
        if (base + TPB < n4) xb = x4[base + TPB];
    }

    // ---- fused table build, warp 0, parallel over lanes, fast-math ----
    if (tid < 32) {
        if (tid < KBINS) {
            sew[tid] = __expf(params[tid]);
            seh[tid] = __expf(params[KBINS + tid]);
        }
        if (tid < KBINS + 1) {
            float v = params[2 * KBINS + tid];
            sD[tid] = __logf(1.0f + __expf(-fabsf(v))) + fmaxf(v, 0.0f) + 1e-5f;
        }
        __syncwarp();
        if (tid == 0) {
            float sw = 0.f, shh = 0.f;
            #pragma unroll
            for (int i = 0; i < KBINS; i++) { sw += sew[i]; shh += seh[i]; }
            float iw = __fdividef(2.0f * TAILB, sw);
            float ih = __fdividef(2.0f * TAILB, shh);
            float aw = -TAILB, ah = -TAILB;
            scw[0] = -TAILB; sch[0] = -TAILB;
            #pragma unroll
            for (int i = 0; i < KBINS; i++) {
                aw = fmaf(sew[i], iw, aw); scw[i + 1] = aw;
                ah = fmaf(seh[i], ih, ah); sch[i + 1] = ah;
            }
        }
        __syncwarp();
        if (tid < KBINS) {
            int bi = tid;
            float xk = scw[bi], yk = sch[bi];
            float Wb = scw[bi + 1] - xk;
            float dy = sch[bi + 1] - yk;
            float dk = sD[bi], dk1 = sD[bi + 1];
            float s  = __fdividef(dy, Wb);
            float c  = dk + dk1 - 2.0f * s;
            float sd = s - dk;
            float a  = __fdividef(1.0f, Wb + 1e-8f);
            float b_ = -a * xk;

            float p2 = -c * a * a;
            float p1 = c * a * (1.0f - 2.0f * b_);
            float p0 = s + c * (b_ - b_ * b_);
            float q2 = dy * sd * a * a + yk * p2;
            float q1 = dy * a * (2.0f * b_ * sd + dk) + yk * p1;
            float q0 = dy * (sd * b_ * b_ + dk * b_) + yk * p0;

            sh[3 * (bi + 1) + 0] = make_float4(p2, p1, p0, q2);
            sh[3 * (bi + 1) + 1] = make_float4(q1, q0, 0.f, 0.f);
        } else if (tid < KBINS + 2) {
            // tail bins 0 and 6: den=1, numz=x
            int bb = (tid == KBINS) ? 0 : (NBINS - 1);
            sh[3 * bb + 0] = make_float4(0.f, 0.f, 1.f, 0.f);
            sh[3 * bb + 1] = make_float4(1.f, 0.f, 0.f, 0.f);
        }
        __syncwarp();
        if (tid < NCELLS) {
            // Build half-cell guess table. Boundaries (transition at x > B):
            //   mB = nextafter(-2.5, -inf)  (encodes x >= -2.5)
            //   scw[1..4]                    (interior)
            //   +2.5                         (upper tail)
            float xL = 0.5f * (float)tid - 3.0f;
            float xR = xL + 0.5f;

            float mB = __int_as_float(__float_as_int(-TAILB) + 1);  // -2.5 - ulp

            // binOf(xL): bin index under the same compare semantics
            int b0 = (xL > mB);
            #pragma unroll
            for (int k = 1; k <= 4; k++) b0 += (xL > scw[k]);
            b0 += (xL > TAILB);

            float bnd = __int_as_float(0x7f800000);  // +inf: no boundary in cell
            if (mB >= xL && mB < xR) bnd = mB;
            #pragma unroll
            for (int k = 1; k <= 4; k++)
                if (scw[k] >= xL && scw[k] < xR) bnd = scw[k];
            if (TAILB >= xL && TAILB < xR) bnd = TAILB;

            sgd[tid] = make_float2(bnd, __int_as_float(b0 * 48));
        }
    }
    __syncthreads();
    // -------------------------------------------------------------------

    const char* shb = (const char*)sh;

    if (full) {
        float4 zv, lv;
        rqs_one(xa.x, sgd, shb, zv.x, lv.x);
        rqs_one(xa.y, sgd, shb, zv.y, lv.y);
        rqs_one(xa.z, sgd, shb, zv.z, lv.z);
        rqs_one(xa.w, sgd, shb, zv.w, lv.w);
        z4[base] = zv;
        l4[base] = lv;

        rqs_one(xb.x, sgd, shb, zv.x, lv.x);
        rqs_one(xb.y, sgd, shb, zv.y, lv.y);
        rqs_one(xb.z, sgd, shb, zv.z, lv.z);
        rqs_one(xb.w, sgd, shb, zv.w, lv.w);
        z4[base + TPB] = zv;
        l4[base + TPB] = lv;
    } else {
        if (base < n4) {
            float4 zv, lv;
            rqs_one(xa.x, sgd, shb, zv.x, lv.x);
            rqs_one(xa.y, sgd, shb, zv.y, lv.y);
            rqs_one(xa.z, sgd, shb, zv.z, lv.z);
            rqs_one(xa.w, sgd, shb, zv.w, lv.w);
            z4[base] = zv;
            l4[base] = lv;
        }
        if (base + TPB < n4) {
            float4 zv, lv;
            rqs_one(xb.x, sgd, shb, zv.x, lv.x);
            rqs_one(xb.y, sgd, shb, zv.y, lv.y);
            rqs_one(xb.z, sgd, shb, zv.z, lv.z);
            rqs_one(xb.w, sgd, shb, zv.w, lv.w);
            z4[base + TPB] = zv;
            l4[base + TPB] = lv;
        }
    }
}

extern "C" void kernel_launch(void* const* d_in, const int* in_sizes, int n_in,
                              void* d_out, int out_size)
{
    const float* x      = (const float*)d_in[0];
    const float* params = (const float*)d_in[1];
    float* out          = (float*)d_out;

    int n  = in_sizes[0];     // 16777216
    int n4 = n >> 2;          // float4 count

    int blocks = (n4 + TPB * VPT - 1) / (TPB * VPT);
    rqs_fused_kernel<<<blocks, TPB>>>(x, params, out, n4);
}